// round 9
// baseline (speedup 1.0000x reference)
#include <cuda_runtime.h>
#include <math.h>

#define RULES 512
#define FEAT  128
#define RES   5
#define BATCH 2048
#define ROWS_PER_BLOCK 16
#define WARPS 32                        // 2 warps per row
#define THREADS (WARPS * 32)            // 1024
#define BLOCKS  (BATCH / ROWS_PER_BLOCK) // 128  (single wave, 1 block/SM)
#define RPL 8                           // rules per lane per warp (half-row)

#define LOG2E 1.4426950408889634f

__device__ __forceinline__ float ex2f(float v) {
    float r;
    asm("ex2.approx.f32 %0, %1;" : "=f"(r) : "f"(v));
    return r;
}

__global__ void __launch_bounds__(THREADS, 1)
fused_kernel(const float* __restrict__ x,
             const float* __restrict__ a,
             const float* __restrict__ bmat,
             const float* __restrict__ r,
             const float* __restrict__ d,
             float* __restrict__ out) {
    // Per-rule constants (fp32, log2-domain K)
    __shared__ float2 sK[RULES];          // (K0*log2e, K1*log2e)
    __shared__ float4 sB[RULES];          // beliefs 0..3
    __shared__ float  sB4[RULES];         // belief 4
    __shared__ float  sS[ROWS_PER_BLOCK][2];      // per-row half activation sums
    __shared__ float  sP[ROWS_PER_BLOCK][2][RES]; // per-row half products

    const int t = threadIdx.x;
    const int l = t & 31;
    const int w = t >> 5;
    const int rowLocal = w >> 1;          // 0..15
    const int half = w & 1;               // which half of the rule set
    const int row = blockIdx.x * ROWS_PER_BLOCK + rowLocal;

    // Issue the global x load FIRST so DRAM latency overlaps the prep phase.
    // Both warps of a pair load the full row (2nd is an L1 hit) — avoids a sync.
    const float4 xv = *reinterpret_cast<const float4*>(x + row * FEAT + l * 4);

    const float ed = __expf(d[0]);
    // ---- prep: thread t handles rule t (first 512 threads) ----
    if (t < RULES) {
        float av = a[t];
        float k1 = 2.0f * ed * av;
        float k0 = r[t] - ed * 128.0f * av * av;
        sK[t] = make_float2(k0 * LOG2E, k1 * LOG2E);

        float bv[RES];
        float m = -1e30f;
        #pragma unroll
        for (int j = 0; j < RES; j++) { bv[j] = bmat[t * RES + j]; m = fmaxf(m, bv[j]); }
        float sum = 0.f;
        #pragma unroll
        for (int j = 0; j < RES; j++) { bv[j] = __expf(bv[j] - m); sum += bv[j]; }
        float inv = 1.0f / sum;
        sB[t] = make_float4(bv[0] * inv, bv[1] * inv, bv[2] * inv, bv[3] * inv);
        sB4[t] = bv[4] * inv;
    }
    __syncthreads();                      // barrier 1: prep done

    // ---- Sx, Sxx over 128 features (x/5); fused pipelined butterfly ----
    float x0 = xv.x * 0.2f, x1 = xv.y * 0.2f, x2 = xv.z * 0.2f, x3 = xv.w * 0.2f;
    float Sx  = x0 + x1 + x2 + x3;
    float Sxx = fmaf(x0, x0, fmaf(x1, x1, fmaf(x2, x2, x3 * x3)));
    #pragma unroll
    for (int o = 16; o; o >>= 1) {
        Sx  += __shfl_xor_sync(0xffffffffu, Sx, o);
        Sxx += __shfl_xor_sync(0xffffffffu, Sxx, o);
    }
    const float C = ed * Sxx * LOG2E;     // common-mode term

    // ---- rule activations for this warp's half (8 rules/lane) ----
    const int rbase = (half << 8) + l;    // half*256 + lane
    float aw[RPL];
    float spart = 0.f;
    #pragma unroll
    for (int i = 0; i < RPL; i++) {
        float2 K = sK[rbase + i * 32];
        aw[i] = ex2f(fmaf(K.y, Sx, K.x) - C);   // dead rules underflow to 0, like ref
        spart += aw[i];
    }
    #pragma unroll
    for (int o = 16; o; o >>= 1) spart += __shfl_xor_sync(0xffffffffu, spart, o);
    if (l == 0) sS[rowLocal][half] = spart;
    __syncthreads();                      // barrier 2: half-sums visible
    const float s = sS[rowLocal][0] + sS[rowLocal][1];

    // ---- evidential combine over this half's rules (R6 proven form) ----
    float p0 = 1.f, p1 = 1.f, p2 = 1.f, p3 = 1.f, p4 = 1.f;
    #pragma unroll
    for (int i = 0; i < RPL; i++) {
        int rr = rbase + i * 32;
        float ratio = __fdividef(aw[i], s - aw[i]);
        float4 b = sB[rr];
        float  b4 = sB4[rr];
        p0 *= fmaf(ratio, b.x, 1.0f);
        p1 *= fmaf(ratio, b.y, 1.0f);
        p2 *= fmaf(ratio, b.z, 1.0f);
        p3 *= fmaf(ratio, b.w, 1.0f);
        p4 *= fmaf(ratio, b4,  1.0f);
    }
    #pragma unroll
    for (int o = 16; o; o >>= 1) {
        p0 *= __shfl_xor_sync(0xffffffffu, p0, o);
        p1 *= __shfl_xor_sync(0xffffffffu, p1, o);
        p2 *= __shfl_xor_sync(0xffffffffu, p2, o);
        p3 *= __shfl_xor_sync(0xffffffffu, p3, o);
        p4 *= __shfl_xor_sync(0xffffffffu, p4, o);
    }
    if (l == 0) {
        sP[rowLocal][half][0] = p0; sP[rowLocal][half][1] = p1;
        sP[rowLocal][half][2] = p2; sP[rowLocal][half][3] = p3;
        sP[rowLocal][half][4] = p4;
    }
    __syncthreads();                      // barrier 3: half-products visible

    // ---- epilogue: one thread per row merges halves ----
    if (t < ROWS_PER_BLOCK) {
        float P[RES];
        #pragma unroll
        for (int j = 0; j < RES; j++) P[j] = sP[t][0][j] * sP[t][1][j];
        float b0 = P[0] - 1.f, b1 = P[1] - 1.f, b2 = P[2] - 1.f,
              b3 = P[3] - 1.f, b4 = P[4] - 1.f;
        float bsum = b0 + b1 + b2 + b3 + b4;
        float acc = fmaf(b0, -0.5f, 0.f);
        acc = fmaf(b2, 0.5f, acc);
        acc = fmaf(b3, 1.0f, acc);
        acc = fmaf(b4, 1.5f, acc);
        out[blockIdx.x * ROWS_PER_BLOCK + t] = __fdividef(acc, bsum);
    }
}

extern "C" void kernel_launch(void* const* d_in, const int* in_sizes, int n_in,
                              void* d_out, int out_size) {
    const float* x = (const float*)d_in[0];
    const float* a = (const float*)d_in[1];
    const float* b = (const float*)d_in[2];
    const float* r = (const float*)d_in[3];
    const float* d = (const float*)d_in[4];
    float* out = (float*)d_out;

    fused_kernel<<<BLOCKS, THREADS>>>(x, a, b, r, d, out);
}

// round 10
// speedup vs baseline: 1.8599x; 1.8599x over previous
#include <cuda_runtime.h>
#include <math.h>

#define RULES 512
#define FEAT  128
#define RES   5
#define BATCH 2048
#define WARPS_PER_BLOCK 16
#define THREADS (WARPS_PER_BLOCK * 32)          // 512 == RULES
#define BLOCKS  (BATCH / WARPS_PER_BLOCK)       // 128  (single wave, 1 block/SM)
#define RPL (RULES / 32)                        // 16 rules per lane

#define LOG2E 1.4426950408889634f

__device__ __forceinline__ float ex2f(float v) {
    float r;
    asm("ex2.approx.f32 %0, %1;" : "=f"(r) : "f"(v));
    return r;
}
__device__ __forceinline__ float rcpf(float v) {
    float r;
    asm("rcp.approx.f32 %0, %1;" : "=f"(r) : "f"(v));
    return r;
}

__global__ void __launch_bounds__(THREADS, 1)
fused_kernel(const float* __restrict__ x,
             const float* __restrict__ a,
             const float* __restrict__ bmat,
             const float* __restrict__ r,
             const float* __restrict__ d,
             float* __restrict__ out) {
    // Per-rule constants. K is log2-domain with the row-common term DROPPED
    // (it cancels in ratio = aw/(s-aw)), and the 1/5 x-scale folded into K1.
    __shared__ float2 sK[RULES];        // (K0*log2e, 0.4*e^d*a*log2e)
    __shared__ float4 sB[RULES];        // beliefs 0..3
    __shared__ float  sB4[RULES];       // belief 4

    const int t = threadIdx.x;
    const int l = t & 31;
    const int w = t >> 5;
    const int row = blockIdx.x * WARPS_PER_BLOCK + w;

    // Issue ALL global loads first; their latency overlaps the Sx butterfly.
    const float4 xv = *reinterpret_cast<const float4*>(x + row * FEAT + l * 4);
    const float av = a[t];
    const float rv = r[t];
    float bv[RES];
    #pragma unroll
    for (int j = 0; j < RES; j++) bv[j] = bmat[t * RES + j];
    const float ed = __expf(d[0]);

    // ---- Sx over raw features (scale folded into K1); butterfly hides prep LDGs
    float Sx = (xv.x + xv.y) + (xv.z + xv.w);
    #pragma unroll
    for (int o = 16; o; o >>= 1) Sx += __shfl_xor_sync(0xffffffffu, Sx, o);

    // ---- prep: thread t handles rule t (THREADS == RULES) ----
    {
        float k1 = 0.4f * ed * av;                  // 2*e^d*a * (1/5)
        float k0 = rv - ed * 128.0f * av * av;      // no common-mode C term
        sK[t] = make_float2(k0 * LOG2E, k1 * LOG2E);

        float m = fmaxf(fmaxf(fmaxf(bv[0], bv[1]), fmaxf(bv[2], bv[3])), bv[4]);
        float sum = 0.f;
        #pragma unroll
        for (int j = 0; j < RES; j++) { bv[j] = ex2f((bv[j] - m) * LOG2E); sum += bv[j]; }
        float inv = rcpf(sum);
        sB[t] = make_float4(bv[0] * inv, bv[1] * inv, bv[2] * inv, bv[3] * inv);
        sB4[t] = bv[4] * inv;
    }
    __syncthreads();                    // the ONLY block barrier

    // ---- rule activations: one FFMA + EX2 each (C dropped, scale-invariant) ----
    float aw[RPL];
    float spart = 0.f;
    #pragma unroll
    for (int i = 0; i < RPL; i++) {
        float2 K = sK[i * 32 + l];
        aw[i] = ex2f(fmaf(K.y, Sx, K.x));
        spart += aw[i];
    }
    #pragma unroll
    for (int o = 16; o; o >>= 1) spart += __shfl_xor_sync(0xffffffffu, spart, o);
    const float s = spart;

    // ---- evidential combine: prod over rules of (ratio*belief + 1) ----
    float p0 = 1.f, p1 = 1.f, p2 = 1.f, p3 = 1.f, p4 = 1.f;
    #pragma unroll
    for (int i = 0; i < RPL; i++) {
        int rr = i * 32 + l;
        float ratio = __fdividef(aw[i], s - aw[i]);
        float4 b = sB[rr];
        float  b4 = sB4[rr];
        p0 *= fmaf(ratio, b.x, 1.0f);
        p1 *= fmaf(ratio, b.y, 1.0f);
        p2 *= fmaf(ratio, b.z, 1.0f);
        p3 *= fmaf(ratio, b.w, 1.0f);
        p4 *= fmaf(ratio, b4,  1.0f);
    }
    // 5 independent cross-lane product reductions (pipelined SHFL chains)
    #pragma unroll
    for (int o = 16; o; o >>= 1) {
        p0 *= __shfl_xor_sync(0xffffffffu, p0, o);
        p1 *= __shfl_xor_sync(0xffffffffu, p1, o);
        p2 *= __shfl_xor_sync(0xffffffffu, p2, o);
        p3 *= __shfl_xor_sync(0xffffffffu, p3, o);
        p4 *= __shfl_xor_sync(0xffffffffu, p4, o);
    }

    if (l == 0) {
        float b0 = p0 - 1.f, b1 = p1 - 1.f, b2 = p2 - 1.f, b3 = p3 - 1.f, b4 = p4 - 1.f;
        float bsum = b0 + b1 + b2 + b3 + b4;
        float acc = fmaf(b0, -0.5f, 0.f);
        acc = fmaf(b2, 0.5f, acc);
        acc = fmaf(b3, 1.0f, acc);
        acc = fmaf(b4, 1.5f, acc);
        out[row] = __fdividef(acc, bsum);
    }
}

extern "C" void kernel_launch(void* const* d_in, const int* in_sizes, int n_in,
                              void* d_out, int out_size) {
    const float* x = (const float*)d_in[0];
    const float* a = (const float*)d_in[1];
    const float* b = (const float*)d_in[2];
    const float* r = (const float*)d_in[3];
    const float* d = (const float*)d_in[4];
    float* out = (float*)d_out;

    fused_kernel<<<BLOCKS, THREADS>>>(x, a, b, r, d, out);
}